// round 2
// baseline (speedup 1.0000x reference)
#include <cuda_runtime.h>
#include <cstdint>
#include <math.h>

#define N_NODES 8192
#define F_DIM   256
#define ALPHA   0.2f

// ---------------- scratch (device globals; no allocation allowed) ------------
__device__ float g_Wh[N_NODES * F_DIM];   // 8 MB
__device__ float g_S1[N_NODES];
__device__ float g_S2[N_NODES];
__device__ float g_E2[N_NODES];
__device__ float g_F2[N_NODES];

// packed f32x2 fma: acc.{lo,hi} += a.{lo,hi} * b.{lo,hi}
__device__ __forceinline__ void ffma2(unsigned long long& acc,
                                      unsigned long long a,
                                      unsigned long long b) {
    asm("fma.rn.f32x2 %0, %1, %2, %0;" : "+l"(acc) : "l"(a), "l"(b));
}
__device__ __forceinline__ unsigned long long dup_f32(float w) {
    unsigned int u = __float_as_uint(w);
    return ((unsigned long long)u << 32) | (unsigned long long)u;
}

// ============================================================================
// Kernel 1: Wh = h @ W + b      (8192x256 @ 256x256)
// block tile 64x64, 256 threads, thread tile 4x4, K-tile 16
// ============================================================================
__global__ __launch_bounds__(256) void k_wh_gemm(const float* __restrict__ h,
                                                 const float* __restrict__ W,
                                                 const float* __restrict__ b) {
    __shared__ float As[16][68];   // [k][m], padded
    __shared__ float Bs[16][64];   // [k][n]

    const int tid = threadIdx.x;
    const int i0 = blockIdx.x * 64;
    const int j0 = blockIdx.y * 64;
    const int tn = tid % 16;       // 16 col groups
    const int tm = tid / 16;       // 16 row groups

    float acc[4][4];
#pragma unroll
    for (int r = 0; r < 4; r++)
#pragma unroll
        for (int c = 0; c < 4; c++) acc[r][c] = 0.f;

    const int arow = tid / 4;           // 0..63
    const int akg  = tid % 4;           // 0..3 (k-group of 4)
    const int bk   = tid / 16;          // 0..15
    const int bcg  = tid % 16;          // 0..15

    for (int k0 = 0; k0 < F_DIM; k0 += 16) {
        float4 av = *(const float4*)&h[(size_t)(i0 + arow) * F_DIM + k0 + akg * 4];
        float4 bv = *(const float4*)&W[(size_t)(k0 + bk) * F_DIM + j0 + bcg * 4];
        __syncthreads();
        As[akg * 4 + 0][arow] = av.x;
        As[akg * 4 + 1][arow] = av.y;
        As[akg * 4 + 2][arow] = av.z;
        As[akg * 4 + 3][arow] = av.w;
        *(float4*)&Bs[bk][bcg * 4] = bv;
        __syncthreads();
#pragma unroll
        for (int kk = 0; kk < 16; kk++) {
            float4 a4 = *(const float4*)&As[kk][tm * 4];
            float4 b4 = *(const float4*)&Bs[kk][tn * 4];
            const float ar[4] = {a4.x, a4.y, a4.z, a4.w};
            const float br[4] = {b4.x, b4.y, b4.z, b4.w};
#pragma unroll
            for (int r = 0; r < 4; r++)
#pragma unroll
                for (int c = 0; c < 4; c++) acc[r][c] += ar[r] * br[c];
        }
    }

    float4 bias = *(const float4*)&b[j0 + tn * 4];
#pragma unroll
    for (int r = 0; r < 4; r++) {
        float4 o;
        o.x = acc[r][0] + bias.x;
        o.y = acc[r][1] + bias.y;
        o.z = acc[r][2] + bias.z;
        o.w = acc[r][3] + bias.w;
        *(float4*)&g_Wh[(size_t)(i0 + tm * 4 + r) * F_DIM + j0 + tn * 4] = o;
    }
}

// ============================================================================
// Kernel 2: s1 = Wh@a1, s2 = Wh@a2, E2 = exp(s2), F2 = exp(alpha*s2)
// one warp per row
// ============================================================================
__global__ __launch_bounds__(256) void k_scores(const float* __restrict__ a) {
    const int row  = blockIdx.x * 8 + (threadIdx.x >> 5);
    const int lane = threadIdx.x & 31;
    float acc1 = 0.f, acc2 = 0.f;
#pragma unroll
    for (int t = 0; t < 8; t++) {
        const int k = lane + t * 32;
        const float w = g_Wh[(size_t)row * F_DIM + k];
        acc1 += w * a[k];
        acc2 += w * a[F_DIM + k];
    }
#pragma unroll
    for (int off = 16; off > 0; off >>= 1) {
        acc1 += __shfl_xor_sync(0xffffffffu, acc1, off);
        acc2 += __shfl_xor_sync(0xffffffffu, acc2, off);
    }
    if (lane == 0) {
        g_S1[row] = acc1;
        g_S2[row] = acc2;
        g_E2[row] = expf(acc2);
        g_F2[row] = expf(ALPHA * acc2);
    }
}

// ============================================================================
// Kernel 3: fused masked softmax + (attention @ Wh)
// block: 32 rows x 256 features, K-tile = 32 j's, 256 threads
// weights built on the fly: w = adj>0 ? (s1+s2>0 ? E1*E2 : F1*F2) : 0
// inner loop uses packed fma.rn.f32x2 (2x fp32 FMA rate)
// ============================================================================
__global__ __launch_bounds__(256, 2) void k_attn_av(const int* __restrict__ adj,
                                                    float* __restrict__ out) {
    __shared__ float Bs[32][256];                      // Wh tile [k][f]     32 KB
    __shared__ unsigned long long Aw2[32][33];         // dup'd weights [k][m] 8.25 KB
    __shared__ float sE1[32], sF1[32], sT1[32], sInv[32];
    __shared__ float sDsum[32][9];

    const int tid = threadIdx.x;
    const int i0  = blockIdx.x * 32;

    if (tid < 32) {
        const float s1v = g_S1[i0 + tid];
        sT1[tid] = -s1v;
        sE1[tid] = expf(s1v);
        sF1[tid] = expf(ALPHA * s1v);
    }

    const int tn = tid & 31;      // lane: feature-pair base (strided by 32 pairs)
    const int tm = tid >> 5;      // warp: row group (4 rows)

    // A-construction mapping: each thread owns row m, 4 consecutive j's
    const int am = tid >> 3;      // 0..31
    const int ajg = tid & 7;      // 0..7  -> j offset ajg*4

    unsigned long long acc[4][4]; // [row rr][pair p]; pair p covers features 2*(tn+32p)+{0,1}
#pragma unroll
    for (int r = 0; r < 4; r++)
#pragma unroll
        for (int p = 0; p < 4; p++) acc[r][p] = 0ull;

    float dsum = 0.f;

    for (int jt = 0; jt < N_NODES / 32; jt++) {
        const int j0 = jt * 32;
        __syncthreads();   // previous tile fully consumed (also orders sE1/sT1 on iter 0)

        // ---- load Wh tile (32 rows x 256 f) : 8 float4 per thread ----
#pragma unroll
        for (int r = 0; r < 8; r++) {
            const int idx = tid + r * 256;
            const int k = idx >> 6;
            const int cg = idx & 63;
            *(float4*)&Bs[k][cg * 4] =
                *(const float4*)&g_Wh[(size_t)(j0 + k) * F_DIM + cg * 4];
        }

        // ---- build weight tile ----
        {
            const int j = j0 + ajg * 4;
            const int4 av = *(const int4*)&adj[(size_t)(i0 + am) * N_NODES + j];
            const float4 s2v = *(const float4*)&g_S2[j];
            const float4 e2v = *(const float4*)&g_E2[j];
            const float4 f2v = *(const float4*)&g_F2[j];
            const float t1 = sT1[am], e1 = sE1[am], f1 = sF1[am];

            const int   ai[4] = {av.x, av.y, av.z, av.w};
            const float s2[4] = {s2v.x, s2v.y, s2v.z, s2v.w};
            const float e2[4] = {e2v.x, e2v.y, e2v.z, e2v.w};
            const float f2[4] = {f2v.x, f2v.y, f2v.z, f2v.w};
#pragma unroll
            for (int s = 0; s < 4; s++) {
                float w = 0.f;
                if (ai[s] > 0) w = (s2[s] > t1) ? (e1 * e2[s]) : (f1 * f2[s]);
                dsum += w;
                Aw2[ajg * 4 + s][am] = dup_f32(w);
            }
        }
        __syncthreads();

        // ---- FFMA2 mainloop ----
#pragma unroll 8
        for (int kk = 0; kk < 32; kk++) {
            unsigned long long a0 = Aw2[kk][tm * 4 + 0];
            unsigned long long a1 = Aw2[kk][tm * 4 + 1];
            unsigned long long a2 = Aw2[kk][tm * 4 + 2];
            unsigned long long a3 = Aw2[kk][tm * 4 + 3];
            unsigned long long b0 = *(const unsigned long long*)&Bs[kk][2 * (tn + 0)];
            unsigned long long b1 = *(const unsigned long long*)&Bs[kk][2 * (tn + 32)];
            unsigned long long b2 = *(const unsigned long long*)&Bs[kk][2 * (tn + 64)];
            unsigned long long b3 = *(const unsigned long long*)&Bs[kk][2 * (tn + 96)];
            ffma2(acc[0][0], a0, b0); ffma2(acc[0][1], a0, b1);
            ffma2(acc[0][2], a0, b2); ffma2(acc[0][3], a0, b3);
            ffma2(acc[1][0], a1, b0); ffma2(acc[1][1], a1, b1);
            ffma2(acc[1][2], a1, b2); ffma2(acc[1][3], a1, b3);
            ffma2(acc[2][0], a2, b0); ffma2(acc[2][1], a2, b1);
            ffma2(acc[2][2], a2, b2); ffma2(acc[2][3], a2, b3);
            ffma2(acc[3][0], a3, b0); ffma2(acc[3][1], a3, b1);
            ffma2(acc[3][2], a3, b2); ffma2(acc[3][3], a3, b3);
        }
    }

    // ---- denominator reduction ----
    __syncthreads();
    sDsum[am][ajg] = dsum;
    __syncthreads();
    if (tid < 32) {
        float s = 0.f;
#pragma unroll
        for (int jg = 0; jg < 8; jg++) s += sDsum[tid][jg];
        sInv[tid] = 1.0f / s;
    }
    __syncthreads();

    // ---- epilogue: normalize + store ----
#pragma unroll
    for (int rr = 0; rr < 4; rr++) {
        const int row = tm * 4 + rr;
        const float inv = sInv[row];
#pragma unroll
        for (int p = 0; p < 4; p++) {
            const unsigned long long v = acc[rr][p];
            float lo = __uint_as_float((unsigned int)(v & 0xffffffffull));
            float hi = __uint_as_float((unsigned int)(v >> 32));
            float2 o;
            o.x = lo * inv;
            o.y = hi * inv;
            *(float2*)&out[(size_t)(i0 + row) * F_DIM + 2 * (tn + 32 * p)] = o;
        }
    }
}

// ============================================================================
extern "C" void kernel_launch(void* const* d_in, const int* in_sizes, int n_in,
                              void* d_out, int out_size) {
    const float* h   = (const float*)d_in[0];
    const int*   adj = (const int*)d_in[1];
    const float* Ww  = (const float*)d_in[2];
    const float* Wb  = (const float*)d_in[3];
    const float* a   = (const float*)d_in[4];
    float* out = (float*)d_out;

    k_wh_gemm<<<dim3(N_NODES / 64, F_DIM / 64), 256>>>(h, Ww, Wb);
    k_scores<<<N_NODES / 8, 256>>>(a);
    k_attn_av<<<N_NODES / 32, 256>>>(adj, out);
}

// round 3
// speedup vs baseline: 1.0965x; 1.0965x over previous
#include <cuda_runtime.h>
#include <cstdint>
#include <math.h>

#define N_NODES 8192
#define F_DIM   256
#define ALPHA   0.2f
#define MB      64      // rows per block in kernel 3
#define KT      32      // j per k-tile
#define NJT     (N_NODES / KT)

// ---------------- scratch (device globals; no allocation allowed) ------------
__device__ float g_Wh[N_NODES * F_DIM];   // 8 MB
__device__ float g_S1[N_NODES];
__device__ float g_S2[N_NODES];
__device__ float g_E2[N_NODES];
__device__ float g_F2[N_NODES];

// packed f32x2 fma: acc.{lo,hi} += a.{lo,hi} * b.{lo,hi}
__device__ __forceinline__ void ffma2(unsigned long long& acc,
                                      unsigned long long a,
                                      unsigned long long b) {
    asm("fma.rn.f32x2 %0, %1, %2, %0;" : "+l"(acc) : "l"(a), "l"(b));
}
__device__ __forceinline__ unsigned long long dup_f32(float w) {
    unsigned int u = __float_as_uint(w);
    return ((unsigned long long)u << 32) | (unsigned long long)u;
}

// ============================================================================
// Kernel 1: Wh = h @ W + b      (8192x256 @ 256x256)
// ============================================================================
__global__ __launch_bounds__(256) void k_wh_gemm(const float* __restrict__ h,
                                                 const float* __restrict__ W,
                                                 const float* __restrict__ b) {
    __shared__ float As[16][68];
    __shared__ float Bs[16][64];

    const int tid = threadIdx.x;
    const int i0 = blockIdx.x * 64;
    const int j0 = blockIdx.y * 64;
    const int tn = tid % 16;
    const int tm = tid / 16;

    float acc[4][4];
#pragma unroll
    for (int r = 0; r < 4; r++)
#pragma unroll
        for (int c = 0; c < 4; c++) acc[r][c] = 0.f;

    const int arow = tid / 4;
    const int akg  = tid % 4;
    const int bk   = tid / 16;
    const int bcg  = tid % 16;

    for (int k0 = 0; k0 < F_DIM; k0 += 16) {
        float4 av = *(const float4*)&h[(size_t)(i0 + arow) * F_DIM + k0 + akg * 4];
        float4 bv = *(const float4*)&W[(size_t)(k0 + bk) * F_DIM + j0 + bcg * 4];
        __syncthreads();
        As[akg * 4 + 0][arow] = av.x;
        As[akg * 4 + 1][arow] = av.y;
        As[akg * 4 + 2][arow] = av.z;
        As[akg * 4 + 3][arow] = av.w;
        *(float4*)&Bs[bk][bcg * 4] = bv;
        __syncthreads();
#pragma unroll
        for (int kk = 0; kk < 16; kk++) {
            float4 a4 = *(const float4*)&As[kk][tm * 4];
            float4 b4 = *(const float4*)&Bs[kk][tn * 4];
            const float ar[4] = {a4.x, a4.y, a4.z, a4.w};
            const float br[4] = {b4.x, b4.y, b4.z, b4.w};
#pragma unroll
            for (int r = 0; r < 4; r++)
#pragma unroll
                for (int c = 0; c < 4; c++) acc[r][c] += ar[r] * br[c];
        }
    }

    float4 bias = *(const float4*)&b[j0 + tn * 4];
#pragma unroll
    for (int r = 0; r < 4; r++) {
        float4 o;
        o.x = acc[r][0] + bias.x;
        o.y = acc[r][1] + bias.y;
        o.z = acc[r][2] + bias.z;
        o.w = acc[r][3] + bias.w;
        *(float4*)&g_Wh[(size_t)(i0 + tm * 4 + r) * F_DIM + j0 + tn * 4] = o;
    }
}

// ============================================================================
// Kernel 2: s1 = Wh@a1, s2 = Wh@a2, E2 = exp(s2), F2 = exp(alpha*s2)
// ============================================================================
__global__ __launch_bounds__(256) void k_scores(const float* __restrict__ a) {
    const int row  = blockIdx.x * 8 + (threadIdx.x >> 5);
    const int lane = threadIdx.x & 31;
    float acc1 = 0.f, acc2 = 0.f;
#pragma unroll
    for (int t = 0; t < 8; t++) {
        const int k = lane + t * 32;
        const float w = g_Wh[(size_t)row * F_DIM + k];
        acc1 += w * a[k];
        acc2 += w * a[F_DIM + k];
    }
#pragma unroll
    for (int off = 16; off > 0; off >>= 1) {
        acc1 += __shfl_xor_sync(0xffffffffu, acc1, off);
        acc2 += __shfl_xor_sync(0xffffffffu, acc2, off);
    }
    if (lane == 0) {
        g_S1[row] = acc1;
        g_S2[row] = acc2;
        g_E2[row] = expf(acc2);
        g_F2[row] = expf(ALPHA * acc2);
    }
}

// ============================================================================
// Kernel 3: fused masked softmax + (attention @ Wh)
// block: 64 rows x 256 features, 256 threads (8 warps), one wave (128 blocks)
// thread tile: 8 rows x 8 features (32 packed f32x2 accumulators)
// full gmem prefetch of next tile (Wh, adj, s2/e2/f2) under the FFMA phase
// ============================================================================
__global__ __launch_bounds__(256, 1) void k_attn_av(const int* __restrict__ adj,
                                                    float* __restrict__ out) {
    __shared__ __align__(16) float Bs[KT][256];                 // 32 KB  [k][f]
    __shared__ __align__(16) unsigned long long Aw2[KT][MB];    // 16 KB  [k][row] dup'd
    __shared__ float sE1[MB], sF1[MB], sT1[MB], sInv[MB];
    __shared__ float sDsum[MB][4];

    const int tid = threadIdx.x;
    const int i0  = blockIdx.x * MB;
    const int w   = tid >> 5;      // warp 0..7 -> rows w*8..w*8+7
    const int l   = tid & 31;      // lane -> features 8l..8l+7

    // weight-build role: thread owns row br, 8 consecutive j's at offset bj
    const int br = tid >> 2;       // 0..63
    const int bj = (tid & 3) * 8;  // 0,8,16,24

    if (tid < MB) {
        const float s1v = g_S1[i0 + tid];
        sT1[tid] = -s1v;
        sE1[tid] = expf(s1v);
        sF1[tid] = expf(ALPHA * s1v);
    }

    unsigned long long acc[8][4];
#pragma unroll
    for (int r = 0; r < 8; r++)
#pragma unroll
        for (int p = 0; p < 4; p++) acc[r][p] = 0ull;

    float dsum = 0.f;

    // ---- prefetch registers (tile jt=0) ----
    float4 whReg[8];
    int4   adjReg[2];
    float4 s2R[2], e2R[2], f2R[2];
    {
#pragma unroll
        for (int r = 0; r < 8; r++) {
            const int id = tid + r * 256;
            const int k = id >> 6, cg = id & 63;
            whReg[r] = *(const float4*)&g_Wh[(size_t)k * F_DIM + cg * 4];
        }
        const size_t arow = (size_t)(i0 + br) * N_NODES + bj;
        adjReg[0] = *(const int4*)&adj[arow];
        adjReg[1] = *(const int4*)&adj[arow + 4];
        s2R[0] = *(const float4*)&g_S2[bj];     s2R[1] = *(const float4*)&g_S2[bj + 4];
        e2R[0] = *(const float4*)&g_E2[bj];     e2R[1] = *(const float4*)&g_E2[bj + 4];
        f2R[0] = *(const float4*)&g_F2[bj];     f2R[1] = *(const float4*)&g_F2[bj + 4];
    }

    for (int jt = 0; jt < NJT; jt++) {
        __syncthreads();  // previous tile fully consumed; sE1/sT1 ready on jt=0

        // ---- STS Wh tile ----
#pragma unroll
        for (int r = 0; r < 8; r++) {
            const int id = tid + r * 256;
            const int k = id >> 6, cg = id & 63;
            *(float4*)&Bs[k][cg * 4] = whReg[r];
        }

        // ---- build weight tile (row br, j's bj..bj+7) ----
        {
            const float t1 = sT1[br], e1 = sE1[br], f1 = sF1[br];
            const int   ai[8] = {adjReg[0].x, adjReg[0].y, adjReg[0].z, adjReg[0].w,
                                 adjReg[1].x, adjReg[1].y, adjReg[1].z, adjReg[1].w};
            const float s2[8] = {s2R[0].x, s2R[0].y, s2R[0].z, s2R[0].w,
                                 s2R[1].x, s2R[1].y, s2R[1].z, s2R[1].w};
            const float e2[8] = {e2R[0].x, e2R[0].y, e2R[0].z, e2R[0].w,
                                 e2R[1].x, e2R[1].y, e2R[1].z, e2R[1].w};
            const float f2[8] = {f2R[0].x, f2R[0].y, f2R[0].z, f2R[0].w,
                                 f2R[1].x, f2R[1].y, f2R[1].z, f2R[1].w};
#pragma unroll
            for (int s = 0; s < 8; s++) {
                float wt = 0.f;
                if (ai[s] > 0) wt = (s2[s] > t1) ? (e1 * e2[s]) : (f1 * f2[s]);
                dsum += wt;
                Aw2[bj + s][br] = dup_f32(wt);
            }
        }
        __syncthreads();

        // ---- prefetch next tile (hidden under the FFMA phase) ----
        if (jt + 1 < NJT) {
            const int jn = (jt + 1) * KT;
#pragma unroll
            for (int r = 0; r < 8; r++) {
                const int id = tid + r * 256;
                const int k = id >> 6, cg = id & 63;
                whReg[r] = *(const float4*)&g_Wh[(size_t)(jn + k) * F_DIM + cg * 4];
            }
            const size_t arow = (size_t)(i0 + br) * N_NODES + jn + bj;
            adjReg[0] = *(const int4*)&adj[arow];
            adjReg[1] = *(const int4*)&adj[arow + 4];
            s2R[0] = *(const float4*)&g_S2[jn + bj]; s2R[1] = *(const float4*)&g_S2[jn + bj + 4];
            e2R[0] = *(const float4*)&g_E2[jn + bj]; e2R[1] = *(const float4*)&g_E2[jn + bj + 4];
            f2R[0] = *(const float4*)&g_F2[jn + bj]; f2R[1] = *(const float4*)&g_F2[jn + bj + 4];
        }

        // ---- FFMA2 mainloop: 8 rows x 4 pairs per thread ----
#pragma unroll 8
        for (int kk = 0; kk < KT; kk++) {
            unsigned long long a[8];
#pragma unroll
            for (int u = 0; u < 4; u++) {
                ulonglong2 v = *(const ulonglong2*)&Aw2[kk][w * 8 + 2 * u];  // broadcast
                a[2 * u]     = v.x;
                a[2 * u + 1] = v.y;
            }
            ulonglong2 b01 = *(const ulonglong2*)&Bs[kk][8 * l];
            ulonglong2 b23 = *(const ulonglong2*)&Bs[kk][8 * l + 4];
            unsigned long long b[4] = {b01.x, b01.y, b23.x, b23.y};
#pragma unroll
            for (int rr = 0; rr < 8; rr++)
#pragma unroll
                for (int p = 0; p < 4; p++) ffma2(acc[rr][p], a[rr], b[p]);
        }
    }

    // ---- denominator reduction ----
    __syncthreads();
    sDsum[br][tid & 3] = dsum;
    __syncthreads();
    if (tid < MB) {
        sInv[tid] = 1.0f / (sDsum[tid][0] + sDsum[tid][1] +
                            sDsum[tid][2] + sDsum[tid][3]);
    }
    __syncthreads();

    // ---- epilogue: normalize + store (features 8l..8l+7 per row) ----
#pragma unroll
    for (int rr = 0; rr < 8; rr++) {
        const int row = w * 8 + rr;
        const float inv = sInv[row];
        float f[8];
#pragma unroll
        for (int p = 0; p < 4; p++) {
            const unsigned long long v = acc[rr][p];
            f[2 * p]     = __uint_as_float((unsigned int)(v & 0xffffffffull)) * inv;
            f[2 * p + 1] = __uint_as_float((unsigned int)(v >> 32)) * inv;
        }
        float4 o0 = {f[0], f[1], f[2], f[3]};
        float4 o1 = {f[4], f[5], f[6], f[7]};
        float* dst = &out[(size_t)(i0 + row) * F_DIM + 8 * l];
        *(float4*)dst = o0;
        *(float4*)(dst + 4) = o1;
    }
}

// ============================================================================
extern "C" void kernel_launch(void* const* d_in, const int* in_sizes, int n_in,
                              void* d_out, int out_size) {
    const float* h   = (const float*)d_in[0];
    const int*   adj = (const int*)d_in[1];
    const float* Ww  = (const float*)d_in[2];
    const float* Wb  = (const float*)d_in[3];
    const float* a   = (const float*)d_in[4];
    float* out = (float*)d_out;

    k_wh_gemm<<<dim3(N_NODES / 64, F_DIM / 64), 256>>>(h, Ww, Wb);
    k_scores<<<N_NODES / 8, 256>>>(a);
    k_attn_av<<<N_NODES / MB, 256>>>(adj, out);
}

// round 5
// speedup vs baseline: 2.9530x; 2.6932x over previous
#include <cuda_runtime.h>
#include <cuda_bf16.h>
#include <cstdint>
#include <math.h>

#define N_NODES 8192
#define F_DIM   256
#define ALPHA   0.2f
#define M_CTA   64
#define KT      32
#define NTILES  (N_NODES / KT)     // 256

// ---------------- scratch (device globals; no allocation allowed) ------------
__device__ float g_Wh[N_NODES * F_DIM];   // 8 MB
__device__ float g_S1[N_NODES];
__device__ float g_S2[N_NODES];
__device__ float g_E2[N_NODES];
__device__ float g_F2[N_NODES];

// ---------------- helpers ----------------------------------------------------
__device__ __forceinline__ uint32_t smem_u32(const void* p) {
    uint32_t a;
    asm("{ .reg .u64 t; cvta.to.shared.u64 t, %1; cvt.u32.u64 %0, t; }"
        : "=r"(a) : "l"(p));
    return a;
}
// pack two f32 -> bf16x2 (lo = a, hi = b)
__device__ __forceinline__ uint32_t packbf(float a, float b) {
    uint32_t r;
    asm("cvt.rn.satfinite.bf16x2.f32 %0, %1, %2;" : "=r"(r) : "f"(b), "f"(a));
    return r;
}
__device__ __forceinline__ float bflo(uint32_t p) { return __uint_as_float(p << 16); }
__device__ __forceinline__ float bfhi(uint32_t p) { return __uint_as_float(p & 0xffff0000u); }

__device__ __forceinline__ void ldsm_x4(uint32_t* r, uint32_t addr) {
    asm volatile("ldmatrix.sync.aligned.m8n8.x4.shared.b16 {%0,%1,%2,%3}, [%4];"
                 : "=r"(r[0]), "=r"(r[1]), "=r"(r[2]), "=r"(r[3]) : "r"(addr));
}
__device__ __forceinline__ void ldsm_x4_t(uint32_t* r, uint32_t addr) {
    asm volatile("ldmatrix.sync.aligned.m8n8.x4.trans.shared.b16 {%0,%1,%2,%3}, [%4];"
                 : "=r"(r[0]), "=r"(r[1]), "=r"(r[2]), "=r"(r[3]) : "r"(addr));
}
__device__ __forceinline__ void mma_bf16(float* c, const uint32_t* a, const uint32_t* b) {
    asm volatile(
        "mma.sync.aligned.m16n8k16.row.col.f32.bf16.bf16.f32 "
        "{%0,%1,%2,%3}, {%4,%5,%6,%7}, {%8,%9}, {%0,%1,%2,%3};"
        : "+f"(c[0]), "+f"(c[1]), "+f"(c[2]), "+f"(c[3])
        : "r"(a[0]), "r"(a[1]), "r"(a[2]), "r"(a[3]), "r"(b[0]), "r"(b[1]));
}

// ============================================================================
// Kernel 1: Wh = h @ W + b
// ============================================================================
__global__ __launch_bounds__(256) void k_wh_gemm(const float* __restrict__ h,
                                                 const float* __restrict__ W,
                                                 const float* __restrict__ b) {
    __shared__ float As[16][68];
    __shared__ float Bs[16][64];
    const int tid = threadIdx.x;
    const int i0 = blockIdx.x * 64, j0 = blockIdx.y * 64;
    const int tn = tid % 16, tm = tid / 16;
    float acc[4][4];
#pragma unroll
    for (int r = 0; r < 4; r++)
#pragma unroll
        for (int c = 0; c < 4; c++) acc[r][c] = 0.f;
    const int arow = tid / 4, akg = tid % 4, bk = tid / 16, bcg = tid % 16;
    for (int k0 = 0; k0 < F_DIM; k0 += 16) {
        float4 av = *(const float4*)&h[(size_t)(i0 + arow) * F_DIM + k0 + akg * 4];
        float4 bv = *(const float4*)&W[(size_t)(k0 + bk) * F_DIM + j0 + bcg * 4];
        __syncthreads();
        As[akg * 4 + 0][arow] = av.x; As[akg * 4 + 1][arow] = av.y;
        As[akg * 4 + 2][arow] = av.z; As[akg * 4 + 3][arow] = av.w;
        *(float4*)&Bs[bk][bcg * 4] = bv;
        __syncthreads();
#pragma unroll
        for (int kk = 0; kk < 16; kk++) {
            float4 a4 = *(const float4*)&As[kk][tm * 4];
            float4 b4 = *(const float4*)&Bs[kk][tn * 4];
            const float ar[4] = {a4.x, a4.y, a4.z, a4.w};
            const float br[4] = {b4.x, b4.y, b4.z, b4.w};
#pragma unroll
            for (int r = 0; r < 4; r++)
#pragma unroll
                for (int c = 0; c < 4; c++) acc[r][c] += ar[r] * br[c];
        }
    }
    float4 bias = *(const float4*)&b[j0 + tn * 4];
#pragma unroll
    for (int r = 0; r < 4; r++) {
        float4 o;
        o.x = acc[r][0] + bias.x; o.y = acc[r][1] + bias.y;
        o.z = acc[r][2] + bias.z; o.w = acc[r][3] + bias.w;
        *(float4*)&g_Wh[(size_t)(i0 + tm * 4 + r) * F_DIM + j0 + tn * 4] = o;
    }
}

// ============================================================================
// Kernel 2: per-node scores + exp tables
// ============================================================================
__global__ __launch_bounds__(256) void k_scores(const float* __restrict__ a) {
    const int row  = blockIdx.x * 8 + (threadIdx.x >> 5);
    const int lane = threadIdx.x & 31;
    float acc1 = 0.f, acc2 = 0.f;
#pragma unroll
    for (int t = 0; t < 8; t++) {
        const int k = lane + t * 32;
        const float w = g_Wh[(size_t)row * F_DIM + k];
        acc1 += w * a[k];
        acc2 += w * a[F_DIM + k];
    }
#pragma unroll
    for (int off = 16; off > 0; off >>= 1) {
        acc1 += __shfl_xor_sync(0xffffffffu, acc1, off);
        acc2 += __shfl_xor_sync(0xffffffffu, acc2, off);
    }
    if (lane == 0) {
        g_S1[row] = acc1;
        g_S2[row] = acc2;
        g_E2[row] = expf(acc2);
        g_F2[row] = expf(ALPHA * acc2);
    }
}

// ============================================================================
// Kernel 3: fused masked-softmax AV GEMM on HMMA (mma.sync bf16, 3-product split)
// CTA: 64 rows x 256 features, 512 threads (16 warps: 2 M-warps x 8 N-warps)
// warp tile 32x32; K-tile 32 j's; SMEM single-buffer with reg prefetch
// ============================================================================
// SMEM layout (dynamic):
//   A_hi [64][40] bf16  @ 0       (row pitch 80 B)   5120 B
//   A_lo                @ 5120                        5120 B
//   B_hi [32][264] bf16 @ 10240   (row pitch 528 B)  16896 B
//   B_lo                @ 27136                       16896 B
#define A_PITCH 80
#define B_PITCH 528
#define OFF_ALO 5120
#define OFF_BHI 10240
#define OFF_BLO 27136
#define SMEM_DYN 44032

__global__ __launch_bounds__(512, 1) void k_attn_av(const int* __restrict__ adj,
                                                    float* __restrict__ out) {
    extern __shared__ __align__(16) char dyn[];
    __shared__ float sDsum[M_CTA][8];
    __shared__ float sInv[M_CTA];

    const int tid = threadIdx.x;
    const int wid = tid >> 5, lane = tid & 31;
    const int i0 = blockIdx.x * M_CTA;

    const uint32_t sBase = smem_u32(dyn);

    // roles
    const int bm = tid >> 3;            // 0..63  weight-build row
    const int bj = (tid & 7) * 4;       // j-chunk (4 j's)
    const int sj = tid >> 4;            // 0..31  B-stage j row
    const int sf = (tid & 15) * 4;      // B-stage f chunk base (+64*g)
    const int m0w = (wid & 1) * 32;     // warp M origin
    const int n0w = (wid >> 1) * 32;    // warp N origin

    // per-thread row constants (single m = bm)
    const float s1 = g_S1[i0 + bm];
    const float e1 = expf(s1), f1 = expf(ALPHA * s1), t1 = -s1;
    float ds = 0.f;

    float acc[2][4][4];                 // [m-frag][n-frag][4]
#pragma unroll
    for (int mf = 0; mf < 2; mf++)
#pragma unroll
        for (int nf = 0; nf < 4; nf++)
#pragma unroll
            for (int c = 0; c < 4; c++) acc[mf][nf][c] = 0.f;

    // ---- prefetch tile 0 ----
    int4 adjv = *(const int4*)&adj[(size_t)(i0 + bm) * N_NODES + bj];
    float4 whv[4];
#pragma unroll
    for (int g = 0; g < 4; g++)
        whv[g] = *(const float4*)&g_Wh[(size_t)sj * F_DIM + sf + 64 * g];
    float4 s2v = *(const float4*)&g_S2[bj];
    float4 e2v = *(const float4*)&g_E2[bj];
    float4 f2v = *(const float4*)&g_F2[bj];

    // ldmatrix lane address components
    const int lr = lane & 15;           // row within 16
    const int lc = lane >> 4;           // 0/1 -> +8 cols

    for (int t = 0; t < NTILES; t++) {
        // ---- build A weights (4 per thread) ----
        {
            const int ai[4] = {adjv.x, adjv.y, adjv.z, adjv.w};
            const float s2a[4] = {s2v.x, s2v.y, s2v.z, s2v.w};
            const float e2a[4] = {e2v.x, e2v.y, e2v.z, e2v.w};
            const float f2a[4] = {f2v.x, f2v.y, f2v.z, f2v.w};
            float wv[4];
#pragma unroll
            for (int c = 0; c < 4; c++) {
                float w = 0.f;
                if (ai[c] > 0) w = (s2a[c] > t1) ? e1 * e2a[c] : f1 * f2a[c];
                wv[c] = w;
            }
            ds += (wv[0] + wv[1]) + (wv[2] + wv[3]);
            const uint32_t h01 = packbf(wv[0], wv[1]);
            const uint32_t h23 = packbf(wv[2], wv[3]);
            const uint32_t l01 = packbf(wv[0] - bflo(h01), wv[1] - bfhi(h01));
            const uint32_t l23 = packbf(wv[2] - bflo(h23), wv[3] - bfhi(h23));
            char* aH = dyn + bm * A_PITCH + bj * 2;
            *(uint2*)aH = make_uint2(h01, h23);
            *(uint2*)(aH + OFF_ALO) = make_uint2(l01, l23);
        }
        // ---- stage B: fp32 -> bf16 hi/lo ----
        {
            char* bH = dyn + OFF_BHI + sj * B_PITCH + sf * 2;
#pragma unroll
            for (int g = 0; g < 4; g++) {
                const float4 v = whv[g];
                const uint32_t h01 = packbf(v.x, v.y);
                const uint32_t h23 = packbf(v.z, v.w);
                const uint32_t l01 = packbf(v.x - bflo(h01), v.y - bfhi(h01));
                const uint32_t l23 = packbf(v.z - bflo(h23), v.w - bfhi(h23));
                *(uint2*)(bH + g * 128) = make_uint2(h01, h23);
                *(uint2*)(bH + g * 128 + (OFF_BLO - OFF_BHI)) = make_uint2(l01, l23);
            }
        }
        __syncthreads();

        // ---- prefetch tile t+1 (overlaps MMA) ----
        if (t + 1 < NTILES) {
            const int jn = (t + 1) * KT;
            adjv = *(const int4*)&adj[(size_t)(i0 + bm) * N_NODES + jn + bj];
#pragma unroll
            for (int g = 0; g < 4; g++)
                whv[g] = *(const float4*)&g_Wh[(size_t)(jn + sj) * F_DIM + sf + 64 * g];
            s2v = *(const float4*)&g_S2[jn + bj];
            e2v = *(const float4*)&g_E2[jn + bj];
            f2v = *(const float4*)&g_F2[jn + bj];
        }

        // ---- MMA phase ----
#pragma unroll
        for (int k16 = 0; k16 < 2; k16++) {
            const int k0 = k16 * 16;
            uint32_t ah[2][4], al[2][4], bb[2][4];
            // A frags: rows m0w + mf*16 + lr, col k0 + 8*lc
#pragma unroll
            for (int mf = 0; mf < 2; mf++) {
                const uint32_t arow = sBase + (m0w + mf * 16 + lr) * A_PITCH + (k0 + 8 * lc) * 2;
                ldsm_x4(ah[mf], arow);
                ldsm_x4(al[mf], arow + OFF_ALO);
            }
            // B hi frags: rows k0 + lr, col n0w + nh*16 + 8*lc
#pragma unroll
            for (int nh = 0; nh < 2; nh++) {
                const uint32_t brow = sBase + OFF_BHI + (k0 + lr) * B_PITCH +
                                      (n0w + nh * 16 + 8 * lc) * 2;
                ldsm_x4_t(bb[nh], brow);
            }
#pragma unroll
            for (int mf = 0; mf < 2; mf++)
#pragma unroll
                for (int nf = 0; nf < 4; nf++) {
                    mma_bf16(acc[mf][nf], ah[mf], &bb[nf >> 1][(nf & 1) * 2]);
                    mma_bf16(acc[mf][nf], al[mf], &bb[nf >> 1][(nf & 1) * 2]);
                }
            // B lo frags (reuse bb)
#pragma unroll
            for (int nh = 0; nh < 2; nh++) {
                const uint32_t brow = sBase + OFF_BLO + (k0 + lr) * B_PITCH +
                                      (n0w + nh * 16 + 8 * lc) * 2;
                ldsm_x4_t(bb[nh], brow);
            }
#pragma unroll
            for (int mf = 0; mf < 2; mf++)
#pragma unroll
                for (int nf = 0; nf < 4; nf++)
                    mma_bf16(acc[mf][nf], ah[mf], &bb[nf >> 1][(nf & 1) * 2]);
        }
        __syncthreads();
    }

    // ---- denominator reduce ----
    sDsum[bm][tid & 7] = ds;
    __syncthreads();
    if (tid < M_CTA) {
        float s = 0.f;
#pragma unroll
        for (int g = 0; g < 8; g++) s += sDsum[tid][g];
        sInv[tid] = 1.0f / s;
    }
    __syncthreads();

    // ---- epilogue: normalize + store ----
#pragma unroll
    for (int mf = 0; mf < 2; mf++) {
        const int r0 = m0w + mf * 16 + (lane >> 2);
        const float inv0 = sInv[r0];
        const float inv1 = sInv[r0 + 8];
#pragma unroll
        for (int nf = 0; nf < 4; nf++) {
            const int col = n0w + nf * 8 + (lane & 3) * 2;
            float2 v0 = {acc[mf][nf][0] * inv0, acc[mf][nf][1] * inv0};
            float2 v1 = {acc[mf][nf][2] * inv1, acc[mf][nf][3] * inv1};
            *(float2*)&out[(size_t)(i0 + r0) * F_DIM + col] = v0;
            *(float2*)&out[(size_t)(i0 + r0 + 8) * F_DIM + col] = v1;
        }
    }
}

// ============================================================================
extern "C" void kernel_launch(void* const* d_in, const int* in_sizes, int n_in,
                              void* d_out, int out_size) {
    const float* h   = (const float*)d_in[0];
    const int*   adj = (const int*)d_in[1];
    const float* Ww  = (const float*)d_in[2];
    const float* Wb  = (const float*)d_in[3];
    const float* a   = (const float*)d_in[4];
    float* out = (float*)d_out;

    k_wh_gemm<<<dim3(N_NODES / 64, F_DIM / 64), 256>>>(h, Ww, Wb);
    k_scores<<<N_NODES / 8, 256>>>(a);
    k_attn_av<<<N_NODES / M_CTA, 512, SMEM_DYN>>>(adj, out);
}

// round 6
// speedup vs baseline: 3.0876x; 1.0456x over previous
#include <cuda_runtime.h>
#include <cuda_bf16.h>
#include <cstdint>
#include <math.h>

#define N_NODES 8192
#define F_DIM   256
#define ALPHA   0.2f
#define M_CTA   64
#define KT      32
#define NTILES  (N_NODES / KT)     // 256

// ---------------- scratch (device globals; no allocation allowed) ------------
__device__ float g_Wh[N_NODES * F_DIM];                  // 8 MB fp32
__device__ __nv_bfloat16 g_Wh_hi[N_NODES * F_DIM];       // 4 MB
__device__ __nv_bfloat16 g_Wh_lo[N_NODES * F_DIM];       // 4 MB
__device__ float g_S1[N_NODES];
__device__ float g_S2[N_NODES];
__device__ float g_E2[N_NODES];
__device__ float g_F2[N_NODES];

// ---------------- helpers ----------------------------------------------------
__device__ __forceinline__ uint32_t smem_u32(const void* p) {
    uint32_t a;
    asm("{ .reg .u64 t; cvta.to.shared.u64 t, %1; cvt.u32.u64 %0, t; }"
        : "=r"(a) : "l"(p));
    return a;
}
// pack two f32 -> bf16x2 (lo = a, hi = b)
__device__ __forceinline__ uint32_t packbf(float a, float b) {
    uint32_t r;
    asm("cvt.rn.satfinite.bf16x2.f32 %0, %1, %2;" : "=r"(r) : "f"(b), "f"(a));
    return r;
}
__device__ __forceinline__ float bflo(uint32_t p) { return __uint_as_float(p << 16); }
__device__ __forceinline__ float bfhi(uint32_t p) { return __uint_as_float(p & 0xffff0000u); }

__device__ __forceinline__ void ldsm_x4(uint32_t* r, uint32_t addr) {
    asm volatile("ldmatrix.sync.aligned.m8n8.x4.shared.b16 {%0,%1,%2,%3}, [%4];"
                 : "=r"(r[0]), "=r"(r[1]), "=r"(r[2]), "=r"(r[3]) : "r"(addr));
}
__device__ __forceinline__ void ldsm_x4_t(uint32_t* r, uint32_t addr) {
    asm volatile("ldmatrix.sync.aligned.m8n8.x4.trans.shared.b16 {%0,%1,%2,%3}, [%4];"
                 : "=r"(r[0]), "=r"(r[1]), "=r"(r[2]), "=r"(r[3]) : "r"(addr));
}
__device__ __forceinline__ void mma_bf16(float* c, const uint32_t* a, const uint32_t* b) {
    asm volatile(
        "mma.sync.aligned.m16n8k16.row.col.f32.bf16.bf16.f32 "
        "{%0,%1,%2,%3}, {%4,%5,%6,%7}, {%8,%9}, {%0,%1,%2,%3};"
        : "+f"(c[0]), "+f"(c[1]), "+f"(c[2]), "+f"(c[3])
        : "r"(a[0]), "r"(a[1]), "r"(a[2]), "r"(a[3]), "r"(b[0]), "r"(b[1]));
}
__device__ __forceinline__ void cp16(uint32_t dst, const void* src) {
    asm volatile("cp.async.cg.shared.global [%0], [%1], 16;"
                 :: "r"(dst), "l"(src) : "memory");
}
#define CP_COMMIT() asm volatile("cp.async.commit_group;" ::: "memory")
#define CP_WAIT0()  asm volatile("cp.async.wait_group 0;" ::: "memory")
#define CP_WAIT1()  asm volatile("cp.async.wait_group 1;" ::: "memory")

// ============================================================================
// Kernel 1: Wh = h @ W + b
// ============================================================================
__global__ __launch_bounds__(256) void k_wh_gemm(const float* __restrict__ h,
                                                 const float* __restrict__ W,
                                                 const float* __restrict__ b) {
    __shared__ float As[16][68];
    __shared__ float Bs[16][64];
    const int tid = threadIdx.x;
    const int i0 = blockIdx.x * 64, j0 = blockIdx.y * 64;
    const int tn = tid % 16, tm = tid / 16;
    float acc[4][4];
#pragma unroll
    for (int r = 0; r < 4; r++)
#pragma unroll
        for (int c = 0; c < 4; c++) acc[r][c] = 0.f;
    const int arow = tid / 4, akg = tid % 4, bk = tid / 16, bcg = tid % 16;
    for (int k0 = 0; k0 < F_DIM; k0 += 16) {
        float4 av = *(const float4*)&h[(size_t)(i0 + arow) * F_DIM + k0 + akg * 4];
        float4 bv = *(const float4*)&W[(size_t)(k0 + bk) * F_DIM + j0 + bcg * 4];
        __syncthreads();
        As[akg * 4 + 0][arow] = av.x; As[akg * 4 + 1][arow] = av.y;
        As[akg * 4 + 2][arow] = av.z; As[akg * 4 + 3][arow] = av.w;
        *(float4*)&Bs[bk][bcg * 4] = bv;
        __syncthreads();
#pragma unroll
        for (int kk = 0; kk < 16; kk++) {
            float4 a4 = *(const float4*)&As[kk][tm * 4];
            float4 b4 = *(const float4*)&Bs[kk][tn * 4];
            const float ar[4] = {a4.x, a4.y, a4.z, a4.w};
            const float br[4] = {b4.x, b4.y, b4.z, b4.w};
#pragma unroll
            for (int r = 0; r < 4; r++)
#pragma unroll
                for (int c = 0; c < 4; c++) acc[r][c] += ar[r] * br[c];
        }
    }
    float4 bias = *(const float4*)&b[j0 + tn * 4];
#pragma unroll
    for (int r = 0; r < 4; r++) {
        float4 o;
        o.x = acc[r][0] + bias.x; o.y = acc[r][1] + bias.y;
        o.z = acc[r][2] + bias.z; o.w = acc[r][3] + bias.w;
        *(float4*)&g_Wh[(size_t)(i0 + tm * 4 + r) * F_DIM + j0 + tn * 4] = o;
    }
}

// ============================================================================
// Kernel 2: per-node scores + exp tables
// ============================================================================
__global__ __launch_bounds__(256) void k_scores(const float* __restrict__ a) {
    const int row  = blockIdx.x * 8 + (threadIdx.x >> 5);
    const int lane = threadIdx.x & 31;
    float acc1 = 0.f, acc2 = 0.f;
#pragma unroll
    for (int t = 0; t < 8; t++) {
        const int k = lane + t * 32;
        const float w = g_Wh[(size_t)row * F_DIM + k];
        acc1 += w * a[k];
        acc2 += w * a[F_DIM + k];
    }
#pragma unroll
    for (int off = 16; off > 0; off >>= 1) {
        acc1 += __shfl_xor_sync(0xffffffffu, acc1, off);
        acc2 += __shfl_xor_sync(0xffffffffu, acc2, off);
    }
    if (lane == 0) {
        g_S1[row] = acc1;
        g_S2[row] = acc2;
        g_E2[row] = expf(acc2);
        g_F2[row] = expf(ALPHA * acc2);
    }
}

// ============================================================================
// Kernel 2b: split Wh fp32 -> bf16 hi/lo (row-major, same layout)
// ============================================================================
__global__ __launch_bounds__(256) void k_split() {
    const int base = (blockIdx.x * 256 + threadIdx.x) * 8;
    const float4 v0 = *(const float4*)&g_Wh[base];
    const float4 v1 = *(const float4*)&g_Wh[base + 4];
    const float v[8] = {v0.x, v0.y, v0.z, v0.w, v1.x, v1.y, v1.z, v1.w};
    uint32_t h[4], l[4];
#pragma unroll
    for (int p = 0; p < 4; p++) {
        h[p] = packbf(v[2 * p], v[2 * p + 1]);
        l[p] = packbf(v[2 * p] - bflo(h[p]), v[2 * p + 1] - bfhi(h[p]));
    }
    *(uint4*)&g_Wh_hi[base] = make_uint4(h[0], h[1], h[2], h[3]);
    *(uint4*)&g_Wh_lo[base] = make_uint4(l[0], l[1], l[2], l[3]);
}

// ============================================================================
// Kernel 3: fused masked-softmax AV GEMM on HMMA (bf16 3-product split)
// CTA: 64 rows x 256 features, 512 threads (2 M-warps x 8 N-warps)
// Double-buffered A (built on the fly) + B (cp.async from precomputed bf16)
// One __syncthreads per tile.
// ============================================================================
#define A_PITCH 80
#define B_PITCH 528
#define ABUF(b)   ((b) * 10240)            // A_hi ; A_lo at +5120
#define BBUF(b)   (20480 + (b) * 33792)    // B_hi ; B_lo at +16896
#define SMEM_DYN  88064

__global__ __launch_bounds__(512, 1) void k_attn_av(const int* __restrict__ adj,
                                                    float* __restrict__ out) {
    extern __shared__ __align__(16) char dyn[];
    __shared__ float sDsum[M_CTA][8];
    __shared__ float sInv[M_CTA];

    const int tid = threadIdx.x;
    const int wid = tid >> 5, lane = tid & 31;
    const int i0 = blockIdx.x * M_CTA;
    const uint32_t sBase = smem_u32(dyn);

    // roles
    const int bm = tid >> 3;            // weight-build row 0..63
    const int bj = (tid & 7) * 4;       // j-chunk
    const int cj = tid >> 4;            // cp.async: j row 0..31
    const int cc = (tid & 15) * 32;     // cp.async: byte offset in 512B row
    const int m0w = (wid & 1) * 32;     // warp M origin
    const int n0w = (wid >> 1) * 32;    // warp N origin

    const float s1 = g_S1[i0 + bm];
    const float e1 = expf(s1), f1 = expf(ALPHA * s1), t1 = -s1;
    float ds = 0.f;

    float acc[2][4][4];
#pragma unroll
    for (int mf = 0; mf < 2; mf++)
#pragma unroll
        for (int nf = 0; nf < 4; nf++)
#pragma unroll
            for (int c = 0; c < 4; c++) acc[mf][nf][c] = 0.f;

    // ---- B tile stage via cp.async ----
    auto stageB = [&](int t, int buf) {
        const size_t gb = ((size_t)(t * KT + cj) * F_DIM) * 2 + cc; // byte offset
        const uint32_t sm = sBase + BBUF(buf) + cj * B_PITCH + cc;
        cp16(sm,         (const char*)g_Wh_hi + gb);
        cp16(sm + 16,    (const char*)g_Wh_hi + gb + 16);
        cp16(sm + 16896,     (const char*)g_Wh_lo + gb);
        cp16(sm + 16896 + 16, (const char*)g_Wh_lo + gb + 16);
        CP_COMMIT();
    };
    // ---- A build (regs -> smem) ----
    auto buildA = [&](int buf, int4 adjv, float4 s2v, float4 e2v, float4 f2v) {
        const int ai[4] = {adjv.x, adjv.y, adjv.z, adjv.w};
        const float s2a[4] = {s2v.x, s2v.y, s2v.z, s2v.w};
        const float e2a[4] = {e2v.x, e2v.y, e2v.z, e2v.w};
        const float f2a[4] = {f2v.x, f2v.y, f2v.z, f2v.w};
        float wv[4];
#pragma unroll
        for (int c = 0; c < 4; c++) {
            float w = 0.f;
            if (ai[c] > 0) w = (s2a[c] > t1) ? e1 * e2a[c] : f1 * f2a[c];
            wv[c] = w;
        }
        ds += (wv[0] + wv[1]) + (wv[2] + wv[3]);
        const uint32_t h01 = packbf(wv[0], wv[1]);
        const uint32_t h23 = packbf(wv[2], wv[3]);
        const uint32_t l01 = packbf(wv[0] - bflo(h01), wv[1] - bfhi(h01));
        const uint32_t l23 = packbf(wv[2] - bflo(h23), wv[3] - bfhi(h23));
        char* aH = dyn + ABUF(buf) + bm * A_PITCH + bj * 2;
        *(uint2*)aH = make_uint2(h01, h23);
        *(uint2*)(aH + 5120) = make_uint2(l01, l23);
    };

    const int lr = lane & 15;
    const int lc = lane >> 4;

    // ---- prologue: tile 0 ----
    {
        stageB(0, 0);
        const int4 adjv = *(const int4*)&adj[(size_t)(i0 + bm) * N_NODES + bj];
        const float4 s2v = *(const float4*)&g_S2[bj];
        const float4 e2v = *(const float4*)&g_E2[bj];
        const float4 f2v = *(const float4*)&g_F2[bj];
        buildA(0, adjv, s2v, e2v, f2v);
    }

    int4 adjv; float4 s2v, e2v, f2v;
    for (int t = 0; t < NTILES; t++) {
        const int cur = t & 1;
        const bool more = (t + 1 < NTILES);

        if (more) {
            const int jn = (t + 1) * KT;
            adjv = *(const int4*)&adj[(size_t)(i0 + bm) * N_NODES + jn + bj];
            s2v = *(const float4*)&g_S2[jn + bj];
            e2v = *(const float4*)&g_E2[jn + bj];
            f2v = *(const float4*)&g_F2[jn + bj];
            stageB(t + 1, cur ^ 1);
            CP_WAIT1();
        } else {
            CP_WAIT0();
        }
        __syncthreads();   // A(t), B(t) visible to all warps

        // ---- MMA on buffers[cur] ----
        const uint32_t aBase  = sBase + ABUF(cur);
        const uint32_t bHiB   = sBase + BBUF(cur);
        const uint32_t bLoB   = bHiB + 16896;
#pragma unroll
        for (int k16 = 0; k16 < 2; k16++) {
            const int k0 = k16 * 16;
            uint32_t ah[2][4], al[2][4], bb[2][4];
#pragma unroll
            for (int mf = 0; mf < 2; mf++) {
                const uint32_t arow = aBase + (m0w + mf * 16 + lr) * A_PITCH + (k0 + 8 * lc) * 2;
                ldsm_x4(ah[mf], arow);
                ldsm_x4(al[mf], arow + 5120);
            }
#pragma unroll
            for (int nh = 0; nh < 2; nh++) {
                const uint32_t brow = bHiB + (k0 + lr) * B_PITCH + (n0w + nh * 16 + 8 * lc) * 2;
                ldsm_x4_t(bb[nh], brow);
            }
#pragma unroll
            for (int mf = 0; mf < 2; mf++)
#pragma unroll
                for (int nf = 0; nf < 4; nf++) {
                    mma_bf16(acc[mf][nf], ah[mf], &bb[nf >> 1][(nf & 1) * 2]);
                    mma_bf16(acc[mf][nf], al[mf], &bb[nf >> 1][(nf & 1) * 2]);
                }
#pragma unroll
            for (int nh = 0; nh < 2; nh++) {
                const uint32_t brow = bLoB + (k0 + lr) * B_PITCH + (n0w + nh * 16 + 8 * lc) * 2;
                ldsm_x4_t(bb[nh], brow);
            }
#pragma unroll
            for (int mf = 0; mf < 2; mf++)
#pragma unroll
                for (int nf = 0; nf < 4; nf++)
                    mma_bf16(acc[mf][nf], ah[mf], &bb[nf >> 1][(nf & 1) * 2]);
        }

        // ---- build A(t+1) into other buffer (no barrier needed) ----
        if (more) buildA(cur ^ 1, adjv, s2v, e2v, f2v);
    }

    // ---- denominator reduce ----
    __syncthreads();
    sDsum[bm][tid & 7] = ds;
    __syncthreads();
    if (tid < M_CTA) {
        float s = 0.f;
#pragma unroll
        for (int g = 0; g < 8; g++) s += sDsum[tid][g];
        sInv[tid] = 1.0f / s;
    }
    __syncthreads();

    // ---- epilogue: normalize + store ----
#pragma unroll
    for (int mf = 0; mf < 2; mf++) {
        const int r0 = m0w + mf * 16 + (lane >> 2);
        const float inv0 = sInv[r0];
        const float inv1 = sInv[r0 + 8];
#pragma unroll
        for (int nf = 0; nf < 4; nf++) {
            const int col = n0w + nf * 8 + (lane & 3) * 2;
            float2 v0 = {acc[mf][nf][0] * inv0, acc[mf][nf][1] * inv0};
            float2 v1 = {acc[mf][nf][2] * inv1, acc[mf][nf][3] * inv1};
            *(float2*)&out[(size_t)(i0 + r0) * F_DIM + col] = v0;
            *(float2*)&out[(size_t)(i0 + r0 + 8) * F_DIM + col] = v1;
        }
    }
}

// ============================================================================
extern "C" void kernel_launch(void* const* d_in, const int* in_sizes, int n_in,
                              void* d_out, int out_size) {
    const float* h   = (const float*)d_in[0];
    const int*   adj = (const int*)d_in[1];
    const float* Ww  = (const float*)d_in[2];
    const float* Wb  = (const float*)d_in[3];
    const float* a   = (const float*)d_in[4];
    float* out = (float*)d_out;

    static int attr_done = 0;
    if (!attr_done) {
        cudaFuncSetAttribute(k_attn_av, cudaFuncAttributeMaxDynamicSharedMemorySize,
                             SMEM_DYN);
        attr_done = 1;
    }

    k_wh_gemm<<<dim3(N_NODES / 64, F_DIM / 64), 256>>>(h, Ww, Wb);
    k_scores<<<N_NODES / 8, 256>>>(a);
    k_split<<<(N_NODES * F_DIM) / (256 * 8), 256>>>();
    k_attn_av<<<N_NODES / M_CTA, 512, SMEM_DYN>>>(adj, out);
}